// round 9
// baseline (speedup 1.0000x reference)
#include <cuda_runtime.h>
#include <cstdint>

// HiddenMarkovModel: 100k 2-state chains x 500 steps, JAX threefry2x32
// (partitionable counter scheme), bit-exact.
// R9 = R8 (1 particle/thread, 3125 warps, TPB=64, prefetched keys, IMAD adds,
// single-add s path, IMAD one-hot/threshold) + pipe balancing: 6 of 20 rotates
// converted to IMAD.WIDE (x * 2^R, opaque multiplier) + single LOP3 (lo|hi)^x0,
// moving 6 ops/iter from the alu pipe (was bound ~92 cyc) to the idle fma pipe
// (target ~41/41 split, ~84 cyc bound).

#define MAX_FRAMES 512

// Per step: A = (k0, k1, ks2, ks2+1), B = (k0+2, k1+3, ks2+4, k0+5)
__device__ uint4    g_keysA[MAX_FRAMES];
__device__ uint4    g_keysB[MAX_FRAMES];
__device__ uint32_t g_thr[2];   // thresholds pre-shifted by 9: [state0, state1]
__device__ uint32_t g_one;      // runtime 1    (opaque -> keeps IMAD)
__device__ uint32_t g_rot13;    // runtime 1<<13 (opaque -> keeps IMAD.WIDE)
__device__ uint32_t g_rot17;    // runtime 1<<17
__device__ uint32_t g_rot26;    // runtime 1<<26

__device__ __forceinline__ void tf2x32_full(uint32_t k0, uint32_t k1,
                                            uint32_t c0, uint32_t c1,
                                            uint32_t& o0, uint32_t& o1) {
    uint32_t ks2 = k0 ^ k1 ^ 0x1BD11BDAu;
    uint32_t x0 = c0 + k0;
    uint32_t x1 = c1 + k1;
#define TF_ROUND(R) { x0 += x1; x1 = __funnelshift_l(x1, x1, (R)); x1 ^= x0; }
    TF_ROUND(13) TF_ROUND(15) TF_ROUND(26) TF_ROUND(6)
    x0 += k1;  x1 += ks2 + 1u;
    TF_ROUND(17) TF_ROUND(29) TF_ROUND(16) TF_ROUND(24)
    x0 += ks2; x1 += k0 + 2u;
    TF_ROUND(13) TF_ROUND(15) TF_ROUND(26) TF_ROUND(6)
    x0 += k0;  x1 += k1 + 3u;
    TF_ROUND(17) TF_ROUND(29) TF_ROUND(16) TF_ROUND(24)
    x0 += k1;  x1 += ks2 + 4u;
    TF_ROUND(13) TF_ROUND(15) TF_ROUND(26) TF_ROUND(6)
    x0 += ks2; x1 += k0 + 5u;
#undef TF_ROUND
    o0 = x0; o1 = x1;
}

// ---------- setup kernel ----------
__global__ void hmm_setup_kernel(const int* __restrict__ seed_ptr, int frames) {
    const uint32_t seed = (uint32_t)seed_ptr[0];
    const uint32_t K0 = 0u, K1 = seed;       // root key (hi, lo)

    uint32_t kp0, kp1, ks0, ks1;
    tf2x32_full(K0, K1, 0u, 0u, kp0, kp1);   // kp
    tf2x32_full(K0, K1, 0u, 1u, ks0, ks1);   // ks

    const int j = threadIdx.x;
    if (j < frames) {
        uint32_t y0, y1;
        tf2x32_full(ks0, ks1, 0u, (uint32_t)j, y0, y1);   // keys[j]
        uint32_t ks2 = y0 ^ y1 ^ 0x1BD11BDAu;
        g_keysA[j] = make_uint4(y0, y1, ks2, ks2 + 1u);
        g_keysB[j] = make_uint4(y0 + 2u, y1 + 3u, ks2 + 4u, y0 + 5u);
    }

    if (j == 0) {
        uint32_t pa, pb;
        tf2x32_full(kp0, kp1, 0u, 0u, pa, pb);
        float u = __uint_as_float(((pa ^ pb) >> 9) | 0x3f800000u) - 1.0f;
        float p = u * 0.001f;
        // u < thr  <=>  (bits>>9) < ceil(thr*2^23)  <=>  bits < (ceil(..) << 9)
        g_thr[0] = ((uint32_t)ceilf(0.2f * 8388608.0f)) << 9;   // state 0
        g_thr[1] = ((uint32_t)ceilf(p    * 8388608.0f)) << 9;   // state 1
        g_one   = 1u;
        g_rot13 = 1u << 13;
        g_rot17 = 1u << 17;
        g_rot26 = 1u << 26;
    }
}

// ---------- main kernel: 1 particle/thread, pipelined key loads ----------
#define TPB 64

// add on the fma pipe: dst = a * one + b  (one == 1, opaque to ptxas)
#define FADD3(dst, a, b) \
    asm("mad.lo.u32 %0, %1, %2, %3;" : "=r"(dst) : "r"(a), "r"(one), "r"(b))
// dst = a * b + c  (all regs) on fma pipe
#define FMAD(dst, a, b, c) \
    asm("mad.lo.u32 %0, %1, %2, %3;" : "=r"(dst) : "r"(a), "r"(b), "r"(c))

// standard round: add(fma) + SHF(alu) + XOR(alu)
#define TF_ROUND(R) { FADD3(x0, x1, x0); \
                      x1 = __funnelshift_l(x1, x1, (R)); x1 ^= x0; }
// wide round: add(fma) + IMAD.WIDE(fma) + LOP3 (lo|hi)^x0 (alu)
#define TF_ROUND_W(mreg) { FADD3(x0, x1, x0); \
    unsigned long long _w; \
    asm("mul.wide.u32 %0, %1, %2;" : "=l"(_w) : "r"(x1), "r"(mreg)); \
    asm("lop3.b32 %0, %1, %2, %3, 0x56;" \
        : "=r"(x1) : "r"((uint32_t)_w), "r"((uint32_t)(_w >> 32)), "r"(x0)); }

__global__ __launch_bounds__(TPB)
void HiddenMarkovModel_kernel(const float* __restrict__ initial,
                              unsigned long long* __restrict__ out,
                              int N, int frames) {
    const int n = blockIdx.x * TPB + threadIdx.x;
    if (n >= N) return;

    const uint32_t one = g_one;            // runtime 1
    const uint32_t m13 = g_rot13;          // runtime 2^13
    const uint32_t m17 = g_rot17;          // runtime 2^17
    const uint32_t m26 = g_rot26;          // runtime 2^26
    const uint32_t T0  = g_thr[0];
    const uint32_t dT  = g_thr[1] - T0;    // thr = T0 + s*dT
    const uint32_t C   = 0x3F800000u;      // 1.0f bits
    const uint32_t nC  = 0u - C;           // -C (o.x = s*(-C)+C)

    // initial one-hot [N,2]: state = 1 iff initial[n,1] set
    const float2 ini = *(const float2*)(initial + 2 * n);
    uint32_t s = (ini.y > 0.5f) ? 1u : 0u;
    const uint32_t base = 2u * (uint32_t)n;          // counter base

    uint2* __restrict__ wp = (uint2*)out + n;

    // software pipeline: keys for iteration i live in qa/qb
    uint4 qa = __ldg(&g_keysA[0]);
    uint4 qb = __ldg(&g_keysB[0]);

#pragma unroll 2
    for (int i = 0; i < frames; ++i) {
        // prefetch next iteration's keys (i+1 <= 500 < MAX_FRAMES)
        const uint4 qa_n = __ldg(&g_keysA[i + 1]);
        const uint4 qb_n = __ldg(&g_keysB[i + 1]);

        // off the s-critical path: base + k1
        uint32_t c0;
        FADD3(c0, base, qa.y);

        // counter (0, base+s): x0 = k0 ; x1 = (base+k1) + s  (one add on s)
        uint32_t x0 = qa.x;
        uint32_t x1;
        FADD3(x1, s, c0);

#define INJ(p0, p1) { FADD3(x0, (p0), x0); FADD3(x1, (p1), x1); }
        // group 1: rotates 13,15,26,6  (13,26 -> wide)
        TF_ROUND_W(m13) TF_ROUND(15) TF_ROUND_W(m26) TF_ROUND(6)
        INJ(qa.y, qa.w)                        // += k1, ks2+1
        // group 2: 17,29,16,24  (17 -> wide)
        TF_ROUND_W(m17) TF_ROUND(29) TF_ROUND(16) TF_ROUND(24)
        INJ(qa.z, qb.x)                        // += ks2, k0+2
        // group 3: 13,15,26,6  (13 -> wide)
        TF_ROUND_W(m13) TF_ROUND(15) TF_ROUND(26) TF_ROUND(6)
        INJ(qa.x, qb.y)                        // += k0, k1+3
        // group 4: 17,29,16,24  (17 -> wide)
        TF_ROUND_W(m17) TF_ROUND(29) TF_ROUND(16) TF_ROUND(24)
        INJ(qa.y, qb.z)                        // += k1, ks2+4
        // group 5: 13,15,26,6  (13 -> wide)
        TF_ROUND_W(m13) TF_ROUND(15) TF_ROUND(26) TF_ROUND(6)
        INJ(qa.z, qb.w)                        // += ks2, k0+5
#undef INJ

        const uint32_t bits = x0 ^ x1;

        uint32_t thr;
        FMAD(thr, s, dT, T0);                  // thr = T0 + s*dT (fma pipe)
        s ^= (bits < thr) ? 1u : 0u;

        // one-hot via IMAD (fma pipe): o.x = s*(-C)+C, o.y = s*C
        uint2 o;
        FMAD(o.x, s, nC, C);
        FMAD(o.y, s, C, 0u);
        *wp = o;                               // coalesced STG.64
        wp += N;

        qa = qa_n; qb = qb_n;                  // rotate pipeline
    }
}

extern "C" void kernel_launch(void* const* d_in, const int* in_sizes, int n_in,
                              void* d_out, int out_size) {
    const float* initial = (const float*)d_in[0];
    const int*   seed    = (const int*)d_in[1];
    const int N      = in_sizes[0] / 2;          // 100000
    const int frames = out_size / in_sizes[0];   // 500

    hmm_setup_kernel<<<1, MAX_FRAMES>>>(seed, frames);

    const int grid = (N + TPB - 1) / TPB;        // 1563 CTAs of 64 threads
    HiddenMarkovModel_kernel<<<grid, TPB>>>(initial,
                                            (unsigned long long*)d_out,
                                            N, frames);
}